// round 1
// baseline (speedup 1.0000x reference)
#include <cuda_runtime.h>

#define D 128
#define MAXN 100096

__device__ float g_hs [MAXN * D];
__device__ float g_acc[MAXN * D];
__device__ float g_buf[MAXN * D];
__device__ int   g_deg[MAXN];
__device__ float g_dis[MAXN];
__device__ int   g_is64;

__global__ void k_detect(const int* __restrict__ e32) {
    if (threadIdx.x == 0 && blockIdx.x == 0) {
        int nz = 0;
        #pragma unroll 1
        for (int i = 0; i < 64; i++) nz += (e32[2 * i + 1] != 0);
        g_is64 = (nz == 0) ? 1 : 0;
    }
}

__global__ void k_init_deg(int n) {
    int i = blockIdx.x * blockDim.x + threadIdx.x;
    if (i < n) g_deg[i] = 1;
}

__global__ void k_count(const void* __restrict__ ep, long long E) {
    long long e = (long long)blockIdx.x * blockDim.x + threadIdx.x;
    if (e >= E) return;
    int r;
    if (g_is64) r = (int)((const long long*)ep)[e];
    else        r = ((const int*)ep)[e];
    atomicAdd(&g_deg[r], 1);
}

__global__ void k_dis(int n) {
    int i = blockIdx.x * blockDim.x + threadIdx.x;
    if (i < n) g_dis[i] = rsqrtf((float)g_deg[i]);
}

__global__ __launch_bounds__(256) void k_gemm(const float* __restrict__ Xin,
                                              const float* __restrict__ W,
                                              const float* __restrict__ B,
                                              int n) {
    const float* X = Xin ? Xin : g_buf;
    __shared__ float Xs[16][132];
    __shared__ float Ws[16][132];
    const int tid = threadIdx.x;
    const int row0 = blockIdx.x * 128;
    const int ty = tid >> 4;
    const int tx = tid & 15;

    float acc[8][8];
    #pragma unroll
    for (int m = 0; m < 8; m++)
        #pragma unroll
        for (int nn = 0; nn < 8; nn++) acc[m][nn] = 0.f;

    for (int k0 = 0; k0 < 128; k0 += 16) {
        #pragma unroll
        for (int i = tid; i < 2048; i += 256) {
            int r = i >> 4;
            int k = i & 15;
            int gr = row0 + r;
            Xs[k][r] = (gr < n) ? X[(long long)gr * 128 + k0 + k] : 0.f;
            Ws[k][r] = W[r * 128 + k0 + k];
        }
        __syncthreads();
        #pragma unroll
        for (int k = 0; k < 16; k++) {
            float xr[8], wr[8];
            #pragma unroll
            for (int m = 0; m < 8; m++)  xr[m] = Xs[k][ty * 8 + m];
            #pragma unroll
            for (int nn = 0; nn < 8; nn++) wr[nn] = Ws[k][tx * 8 + nn];
            #pragma unroll
            for (int m = 0; m < 8; m++)
                #pragma unroll
                for (int nn = 0; nn < 8; nn++)
                    acc[m][nn] += xr[m] * wr[nn];
        }
        __syncthreads();
    }

    #pragma unroll
    for (int m = 0; m < 8; m++) {
        int gi = row0 + ty * 8 + m;
        if (gi >= n) continue;
        float dv = g_dis[gi];
        #pragma unroll
        for (int nn = 0; nn < 8; nn++) {
            int j = tx * 8 + nn;
            long long o = (long long)gi * 128 + j;
            g_hs[o]  = dv * (acc[m][nn] + B[j]);
            g_acc[o] = 0.f;
        }
    }
}

__global__ __launch_bounds__(256) void k_scatter(const void* __restrict__ ep,
                                                 long long E) {
    long long gt = (long long)blockIdx.x * blockDim.x + threadIdx.x;
    long long e = gt >> 5;
    if (e >= E) return;
    const int lane = threadIdx.x & 31;
    long long r, c;
    if (g_is64) {
        const long long* p = (const long long*)ep;
        r = p[e]; c = p[e + E];
    } else {
        const int* p = (const int*)ep;
        r = p[e]; c = p[e + E];
    }
    const float4 v = *(const float4*)(&g_hs[r * 128 + lane * 4]);
    float* dst = &g_acc[c * 128 + lane * 4];
    asm volatile("red.global.add.v4.f32 [%0], {%1,%2,%3,%4};"
                 :: "l"(dst), "f"(v.x), "f"(v.y), "f"(v.z), "f"(v.w)
                 : "memory");
}

__global__ __launch_bounds__(256) void k_final(float* __restrict__ dst,
                                               int to_buf, int n) {
    long long t = (long long)blockIdx.x * blockDim.x + threadIdx.x;
    if (t >= (long long)n * 32) return;
    long long i = t >> 5;
    float dv = g_dis[i];
    float4 a = *(const float4*)(&g_acc[t * 4]);
    float4 h = *(const float4*)(&g_hs[t * 4]);
    float4 o;
    o.x = fmaxf(dv * (a.x + h.x), 0.f);
    o.y = fmaxf(dv * (a.y + h.y), 0.f);
    o.z = fmaxf(dv * (a.z + h.z), 0.f);
    o.w = fmaxf(dv * (a.w + h.w), 0.f);
    float* out = to_buf ? g_buf : dst;
    *(float4*)(&out[t * 4]) = o;
}

extern "C" void kernel_launch(void* const* d_in, const int* in_sizes, int n_in,
                              void* d_out, int out_size) {
    const float* x  = (const float*)d_in[0];
    const void*  ep = d_in[1];
    const float* W1 = (const float*)d_in[2];
    const float* b1 = (const float*)d_in[3];
    const float* W2 = (const float*)d_in[4];
    const float* b2 = (const float*)d_in[5];
    const float* W3 = (const float*)d_in[6];
    const float* b3 = (const float*)d_in[7];
    float* out = (float*)d_out;

    const int n = in_sizes[0] / D;
    const long long E = (long long)in_sizes[1] / 2;

    const int tb = 256;
    const int nb_n    = (n + tb - 1) / tb;
    const int nb_e    = (int)((E + tb - 1) / tb);
    const int nb_gemm = (n + 127) / 128;
    const int nb_scat = (int)((E * 32 + tb - 1) / tb);
    const int nb_fin  = (int)(((long long)n * 32 + tb - 1) / tb);

    k_detect<<<1, 32>>>((const int*)ep);
    k_init_deg<<<nb_n, tb>>>(n);
    k_count<<<nb_e, tb>>>(ep, E);
    k_dis<<<nb_n, tb>>>(n);

    k_gemm<<<nb_gemm, 256>>>(x, W1, b1, n);
    k_scatter<<<nb_scat, tb>>>(ep, E);
    k_final<<<nb_fin, tb>>>(out, 1, n);

    k_gemm<<<nb_gemm, 256>>>(nullptr, W2, b2, n);
    k_scatter<<<nb_scat, tb>>>(ep, E);
    k_final<<<nb_fin, tb>>>(out, 1, n);

    k_gemm<<<nb_gemm, 256>>>(nullptr, W3, b3, n);
    k_scatter<<<nb_scat, tb>>>(ep, E);
    k_final<<<nb_fin, tb>>>(out, 0, n);
}

// round 2
// speedup vs baseline: 1.6410x; 1.6410x over previous
#include <cuda_runtime.h>

#define D 128
#define MAXN 100096
#define EMAX 1700000

__device__ float g_hs [MAXN * D];   // dis[i] * (x W^T + b)
__device__ float g_buf[MAXN * D];   // layer output -> next layer input
__device__ int   g_deg[MAXN];       // out-degree (by row) + self-loop, for dis
__device__ int   g_indeg[MAXN];     // in-degree (by col), for CSR
__device__ int   g_off[MAXN + 1];   // CSR offsets (exclusive)
__device__ int   g_pos[MAXN];       // fill cursors
__device__ int   g_csr[EMAX];       // CSR source indices
__device__ float g_dis[MAXN];
__device__ int   g_is64;

// --------------------------------------------------------------------------
// edge dtype detection (int64 vs int32): values < 2^31 LE -> odd words all 0
// --------------------------------------------------------------------------
__global__ void k_detect(const int* __restrict__ e32) {
    if (threadIdx.x == 0 && blockIdx.x == 0) {
        int nz = 0;
        #pragma unroll 1
        for (int i = 0; i < 64; i++) nz += (e32[2 * i + 1] != 0);
        g_is64 = (nz == 0) ? 1 : 0;
    }
}

__global__ void k_init(int n) {
    int i = blockIdx.x * blockDim.x + threadIdx.x;
    if (i < n) { g_deg[i] = 1; g_indeg[i] = 0; }
}

__global__ void k_count(const void* __restrict__ ep, long long E) {
    long long e = (long long)blockIdx.x * blockDim.x + threadIdx.x;
    if (e >= E) return;
    int r, c;
    if (g_is64) {
        const long long* p = (const long long*)ep;
        r = (int)p[e]; c = (int)p[e + E];
    } else {
        const int* p = (const int*)ep;
        r = p[e]; c = p[e + E];
    }
    atomicAdd(&g_deg[r], 1);
    atomicAdd(&g_indeg[c], 1);
}

__global__ void k_dis(int n) {
    int i = blockIdx.x * blockDim.x + threadIdx.x;
    if (i < n) g_dis[i] = rsqrtf((float)g_deg[i]);
}

// --------------------------------------------------------------------------
// single-block exclusive scan of g_indeg -> g_off, g_pos ; g_off[n] = total
// --------------------------------------------------------------------------
__global__ __launch_bounds__(1024) void k_scan(int n) {
    __shared__ int s[1024];
    const int t = threadIdx.x;
    const int chunk = (n + 1023) / 1024;
    const int start = t * chunk;
    const int end = min(start + chunk, n);
    int sum = 0;
    for (int i = start; i < end; i++) sum += g_indeg[i];
    s[t] = sum;
    __syncthreads();
    // Hillis-Steele inclusive scan
    for (int o = 1; o < 1024; o <<= 1) {
        int v = (t >= o) ? s[t - o] : 0;
        __syncthreads();
        s[t] += v;
        __syncthreads();
    }
    int run = (t == 0) ? 0 : s[t - 1];
    for (int i = start; i < end; i++) {
        g_off[i] = run;
        g_pos[i] = run;
        run += g_indeg[i];
    }
    if (t == 1023) g_off[n] = s[1023];
}

__global__ void k_fill(const void* __restrict__ ep, long long E) {
    long long e = (long long)blockIdx.x * blockDim.x + threadIdx.x;
    if (e >= E) return;
    int r, c;
    if (g_is64) {
        const long long* p = (const long long*)ep;
        r = (int)p[e]; c = (int)p[e + E];
    } else {
        const int* p = (const int*)ep;
        r = p[e]; c = p[e + E];
    }
    int p = atomicAdd(&g_pos[c], 1);
    g_csr[p] = r;
}

// --------------------------------------------------------------------------
// SGEMM: g_hs[i,j] = dis[i] * (X W^T + b)[i,j]
// --------------------------------------------------------------------------
__global__ __launch_bounds__(256) void k_gemm(const float* __restrict__ Xin,
                                              const float* __restrict__ W,
                                              const float* __restrict__ B,
                                              int n) {
    const float* X = Xin ? Xin : g_buf;
    __shared__ float Xs[16][132];
    __shared__ float Ws[16][132];
    const int tid = threadIdx.x;
    const int row0 = blockIdx.x * 128;
    const int ty = tid >> 4;
    const int tx = tid & 15;

    float acc[8][8];
    #pragma unroll
    for (int m = 0; m < 8; m++)
        #pragma unroll
        for (int nn = 0; nn < 8; nn++) acc[m][nn] = 0.f;

    for (int k0 = 0; k0 < 128; k0 += 16) {
        #pragma unroll
        for (int i = tid; i < 2048; i += 256) {
            int r = i >> 4;
            int k = i & 15;
            int gr = row0 + r;
            Xs[k][r] = (gr < n) ? X[(long long)gr * 128 + k0 + k] : 0.f;
            Ws[k][r] = W[r * 128 + k0 + k];
        }
        __syncthreads();
        #pragma unroll
        for (int k = 0; k < 16; k++) {
            float xr[8], wr[8];
            #pragma unroll
            for (int m = 0; m < 8; m++)  xr[m] = Xs[k][ty * 8 + m];
            #pragma unroll
            for (int nn = 0; nn < 8; nn++) wr[nn] = Ws[k][tx * 8 + nn];
            #pragma unroll
            for (int m = 0; m < 8; m++)
                #pragma unroll
                for (int nn = 0; nn < 8; nn++)
                    acc[m][nn] += xr[m] * wr[nn];
        }
        __syncthreads();
    }

    #pragma unroll
    for (int m = 0; m < 8; m++) {
        int gi = row0 + ty * 8 + m;
        if (gi >= n) continue;
        float dv = g_dis[gi];
        #pragma unroll
        for (int nn = 0; nn < 8; nn++) {
            int j = tx * 8 + nn;
            g_hs[(long long)gi * 128 + j] = dv * (acc[m][nn] + B[j]);
        }
    }
}

// --------------------------------------------------------------------------
// Pull aggregation, fused with finalize:
// out[c,:] = relu( dis[c] * ( sum_{e in CSR[c]} hs[src_e,:] + hs[c,:] ) )
// one warp per node, float4 per lane
// --------------------------------------------------------------------------
__global__ __launch_bounds__(256) void k_agg(float* __restrict__ dst,
                                             int to_buf, int n) {
    const int node = blockIdx.x * 8 + (threadIdx.x >> 5);
    if (node >= n) return;
    const int lane = threadIdx.x & 31;
    const int col4 = lane * 4;

    const int beg = g_off[node];
    const int end = g_off[node + 1];

    // self-loop term
    float4 acc = *(const float4*)(&g_hs[node * 128 + col4]);

    int j = beg;
    for (; j + 4 <= end; j += 4) {
        int i0 = g_csr[j + 0];
        int i1 = g_csr[j + 1];
        int i2 = g_csr[j + 2];
        int i3 = g_csr[j + 3];
        float4 v0 = *(const float4*)(&g_hs[i0 * 128 + col4]);
        float4 v1 = *(const float4*)(&g_hs[i1 * 128 + col4]);
        float4 v2 = *(const float4*)(&g_hs[i2 * 128 + col4]);
        float4 v3 = *(const float4*)(&g_hs[i3 * 128 + col4]);
        acc.x += v0.x + v1.x + v2.x + v3.x;
        acc.y += v0.y + v1.y + v2.y + v3.y;
        acc.z += v0.z + v1.z + v2.z + v3.z;
        acc.w += v0.w + v1.w + v2.w + v3.w;
    }
    for (; j < end; j++) {
        int i0 = g_csr[j];
        float4 v0 = *(const float4*)(&g_hs[i0 * 128 + col4]);
        acc.x += v0.x; acc.y += v0.y; acc.z += v0.z; acc.w += v0.w;
    }

    const float dv = g_dis[node];
    float4 o;
    o.x = fmaxf(dv * acc.x, 0.f);
    o.y = fmaxf(dv * acc.y, 0.f);
    o.z = fmaxf(dv * acc.z, 0.f);
    o.w = fmaxf(dv * acc.w, 0.f);

    float* out = to_buf ? g_buf : dst;
    *(float4*)(&out[node * 128 + col4]) = o;
}

// --------------------------------------------------------------------------
extern "C" void kernel_launch(void* const* d_in, const int* in_sizes, int n_in,
                              void* d_out, int out_size) {
    const float* x  = (const float*)d_in[0];
    const void*  ep = d_in[1];
    const float* W1 = (const float*)d_in[2];
    const float* b1 = (const float*)d_in[3];
    const float* W2 = (const float*)d_in[4];
    const float* b2 = (const float*)d_in[5];
    const float* W3 = (const float*)d_in[6];
    const float* b3 = (const float*)d_in[7];
    float* out = (float*)d_out;

    const int n = in_sizes[0] / D;
    const long long E = (long long)in_sizes[1] / 2;

    const int tb = 256;
    const int nb_n    = (n + tb - 1) / tb;
    const int nb_e    = (int)((E + tb - 1) / tb);
    const int nb_gemm = (n + 127) / 128;
    const int nb_agg  = (n + 7) / 8;

    // graph preprocessing (rebuilt every call: deterministic work)
    k_detect<<<1, 32>>>((const int*)ep);
    k_init<<<nb_n, tb>>>(n);
    k_count<<<nb_e, tb>>>(ep, E);
    k_dis<<<nb_n, tb>>>(n);
    k_scan<<<1, 1024>>>(n);
    k_fill<<<nb_e, tb>>>(ep, E);

    // layer 1
    k_gemm<<<nb_gemm, 256>>>(x, W1, b1, n);
    k_agg<<<nb_agg, 256>>>(out, 1, n);
    // layer 2
    k_gemm<<<nb_gemm, 256>>>(nullptr, W2, b2, n);
    k_agg<<<nb_agg, 256>>>(out, 1, n);
    // layer 3
    k_gemm<<<nb_gemm, 256>>>(nullptr, W3, b3, n);
    k_agg<<<nb_agg, 256>>>(out, 0, n);
}

// round 3
// speedup vs baseline: 1.7256x; 1.0516x over previous
#include <cuda_runtime.h>
#include <cstdint>

#define D 128
#define MAXN 100096
#define EMAX 1700000

__device__ float g_hs [MAXN * D];   // dis[i] * (x W^T + b)
__device__ float g_buf[MAXN * D];   // layer output -> next layer input
__device__ int   g_deg[MAXN];       // out-degree (row) + self-loop, for dis
__device__ int   g_indeg[MAXN];     // in-degree (col), for CSR
__device__ int   g_off[MAXN + 1];   // CSR offsets
__device__ int   g_pos[MAXN];       // fill cursors
__device__ int   g_csr[EMAX];       // CSR source indices
__device__ float g_dis[MAXN];
__device__ int   g_is64;

// --------------------------------------------------------------------------
// edge dtype detection (int64 vs int32)
// --------------------------------------------------------------------------
__global__ void k_detect(const int* __restrict__ e32) {
    if (threadIdx.x == 0 && blockIdx.x == 0) {
        int nz = 0;
        #pragma unroll 1
        for (int i = 0; i < 64; i++) nz += (e32[2 * i + 1] != 0);
        g_is64 = (nz == 0) ? 1 : 0;
    }
}

__global__ void k_init(int n) {
    int i = blockIdx.x * blockDim.x + threadIdx.x;
    if (i < n) { g_deg[i] = 1; g_indeg[i] = 0; }
}

__global__ void k_count(const void* __restrict__ ep, long long E) {
    long long e = (long long)blockIdx.x * blockDim.x + threadIdx.x;
    if (e >= E) return;
    int r, c;
    if (g_is64) {
        const long long* p = (const long long*)ep;
        r = (int)p[e]; c = (int)p[e + E];
    } else {
        const int* p = (const int*)ep;
        r = p[e]; c = p[e + E];
    }
    atomicAdd(&g_deg[r], 1);
    atomicAdd(&g_indeg[c], 1);
}

__global__ void k_dis(int n) {
    int i = blockIdx.x * blockDim.x + threadIdx.x;
    if (i < n) g_dis[i] = rsqrtf((float)g_deg[i]);
}

__global__ __launch_bounds__(1024) void k_scan(int n) {
    __shared__ int s[1024];
    const int t = threadIdx.x;
    const int chunk = (n + 1023) / 1024;
    const int start = t * chunk;
    const int end = min(start + chunk, n);
    int sum = 0;
    for (int i = start; i < end; i++) sum += g_indeg[i];
    s[t] = sum;
    __syncthreads();
    for (int o = 1; o < 1024; o <<= 1) {
        int v = (t >= o) ? s[t - o] : 0;
        __syncthreads();
        s[t] += v;
        __syncthreads();
    }
    int run = (t == 0) ? 0 : s[t - 1];
    for (int i = start; i < end; i++) {
        g_off[i] = run;
        g_pos[i] = run;
        run += g_indeg[i];
    }
    if (t == 1023) g_off[n] = s[1023];
}

__global__ void k_fill(const void* __restrict__ ep, long long E) {
    long long e = (long long)blockIdx.x * blockDim.x + threadIdx.x;
    if (e >= E) return;
    int r, c;
    if (g_is64) {
        const long long* p = (const long long*)ep;
        r = (int)p[e]; c = (int)p[e + E];
    } else {
        const int* p = (const int*)ep;
        r = p[e]; c = p[e + E];
    }
    int p = atomicAdd(&g_pos[c], 1);
    g_csr[p] = r;
}

// --------------------------------------------------------------------------
// 3xTF32 tensor-core GEMM:  g_hs[i,j] = dis[i] * ((X W^T)[i,j] + b[j])
// BM=BN=128, BK=16, 256 threads (8 warps, 4x2), warp tile 32x64
// --------------------------------------------------------------------------
__device__ __forceinline__ float tf32_rna(float x) {
    uint32_t u;
    asm("cvt.rna.tf32.f32 %0, %1;" : "=r"(u) : "f"(x));
    return __uint_as_float(u);
}

__device__ __forceinline__ void mma_tf32(float c[4], const float a[4], const float b[2]) {
    const uint32_t* A = reinterpret_cast<const uint32_t*>(a);
    const uint32_t* Bp = reinterpret_cast<const uint32_t*>(b);
    asm volatile(
        "mma.sync.aligned.m16n8k8.row.col.f32.tf32.tf32.f32 "
        "{%0,%1,%2,%3}, {%4,%5,%6,%7}, {%8,%9}, {%0,%1,%2,%3};"
        : "+f"(c[0]), "+f"(c[1]), "+f"(c[2]), "+f"(c[3])
        : "r"(A[0]), "r"(A[1]), "r"(A[2]), "r"(A[3]), "r"(Bp[0]), "r"(Bp[1]));
}

#define BK 16
#define SP 132

__global__ __launch_bounds__(256) void k_gemm(const float* __restrict__ Xin,
                                              const float* __restrict__ W,
                                              const float* __restrict__ Bv,
                                              int n) {
    const float* X = Xin ? Xin : g_buf;
    __shared__ float sXhi[BK][SP], sXlo[BK][SP];
    __shared__ float sWhi[BK][SP], sWlo[BK][SP];

    const int tid  = threadIdx.x;
    const int lane = tid & 31;
    const int wid  = tid >> 5;
    const int warpRow = wid >> 1;   // 0..3
    const int warpCol = wid & 1;    // 0..1
    const int row0 = blockIdx.x * 128;
    const int lr = lane >> 2;       // 0..7
    const int lq = lane & 3;        // 0..3

    float c[2][8][4];
    #pragma unroll
    for (int mt = 0; mt < 2; mt++)
        #pragma unroll
        for (int nt = 0; nt < 8; nt++)
            #pragma unroll
            for (int q = 0; q < 4; q++) c[mt][nt][q] = 0.f;

    for (int k0 = 0; k0 < 128; k0 += BK) {
        #pragma unroll
        for (int it = 0; it < 2; it++) {
            int idx = it * 256 + tid;       // 0..511
            int r = idx >> 2;               // 0..127
            int kq = (idx & 3) * 4;         // 0,4,8,12
            int gr = row0 + r;
            float4 xv = (gr < n) ? *(const float4*)&X[(long long)gr * 128 + k0 + kq]
                                 : make_float4(0.f, 0.f, 0.f, 0.f);
            float4 wv = *(const float4*)&W[r * 128 + k0 + kq];
            float xe[4] = {xv.x, xv.y, xv.z, xv.w};
            float we[4] = {wv.x, wv.y, wv.z, wv.w};
            #pragma unroll
            for (int q = 0; q < 4; q++) {
                float xh = tf32_rna(xe[q]);
                float wh = tf32_rna(we[q]);
                sXhi[kq + q][r] = xh;
                sXlo[kq + q][r] = tf32_rna(xe[q] - xh);
                sWhi[kq + q][r] = wh;
                sWlo[kq + q][r] = tf32_rna(we[q] - wh);
            }
        }
        __syncthreads();

        #pragma unroll
        for (int kk = 0; kk < BK; kk += 8) {
            // A fragments: rows warpRow*32 + mt*16 + {lr, lr+8}, k = kk + {lq, lq+4}
            float ahi[2][4], alo[2][4];
            #pragma unroll
            for (int mt = 0; mt < 2; mt++) {
                int r = warpRow * 32 + mt * 16 + lr;
                ahi[mt][0] = sXhi[kk + lq][r];
                ahi[mt][1] = sXhi[kk + lq][r + 8];
                ahi[mt][2] = sXhi[kk + lq + 4][r];
                ahi[mt][3] = sXhi[kk + lq + 4][r + 8];
                alo[mt][0] = sXlo[kk + lq][r];
                alo[mt][1] = sXlo[kk + lq][r + 8];
                alo[mt][2] = sXlo[kk + lq + 4][r];
                alo[mt][3] = sXlo[kk + lq + 4][r + 8];
            }
            #pragma unroll
            for (int nt = 0; nt < 8; nt++) {
                int col = warpCol * 64 + nt * 8 + lr;
                float bhi[2], blo[2];
                bhi[0] = sWhi[kk + lq][col];
                bhi[1] = sWhi[kk + lq + 4][col];
                blo[0] = sWlo[kk + lq][col];
                blo[1] = sWlo[kk + lq + 4][col];
                #pragma unroll
                for (int mt = 0; mt < 2; mt++) {
                    mma_tf32(c[mt][nt], ahi[mt], bhi);
                    mma_tf32(c[mt][nt], ahi[mt], blo);
                    mma_tf32(c[mt][nt], alo[mt], bhi);
                }
            }
        }
        __syncthreads();
    }

    // epilogue: hs[gi, col] = dis[gi] * (c + bias[col])
    #pragma unroll
    for (int mt = 0; mt < 2; mt++) {
        #pragma unroll
        for (int half = 0; half < 2; half++) {
            int gi = row0 + warpRow * 32 + mt * 16 + lr + half * 8;
            if (gi >= n) continue;
            float dv = g_dis[gi];
            #pragma unroll
            for (int nt = 0; nt < 8; nt++) {
                int col = warpCol * 64 + nt * 8 + lq * 2;
                float2 o;
                o.x = dv * (c[mt][nt][half * 2 + 0] + Bv[col]);
                o.y = dv * (c[mt][nt][half * 2 + 1] + Bv[col + 1]);
                *(float2*)&g_hs[(long long)gi * 128 + col] = o;
            }
        }
    }
}

// --------------------------------------------------------------------------
// Pull aggregation fused with finalize:
// out[c,:] = relu( dis[c] * ( sum_{src in CSR[c]} hs[src,:] + hs[c,:] ) )
// --------------------------------------------------------------------------
__global__ __launch_bounds__(256) void k_agg(float* __restrict__ dst,
                                             int to_buf, int n) {
    const int node = blockIdx.x * 8 + (threadIdx.x >> 5);
    if (node >= n) return;
    const int lane = threadIdx.x & 31;
    const int col4 = lane * 4;

    const int beg = g_off[node];
    const int end = g_off[node + 1];

    float4 acc = *(const float4*)(&g_hs[node * 128 + col4]);  // self-loop

    int j = beg;
    for (; j + 4 <= end; j += 4) {
        int i0 = g_csr[j + 0];
        int i1 = g_csr[j + 1];
        int i2 = g_csr[j + 2];
        int i3 = g_csr[j + 3];
        float4 v0 = *(const float4*)(&g_hs[i0 * 128 + col4]);
        float4 v1 = *(const float4*)(&g_hs[i1 * 128 + col4]);
        float4 v2 = *(const float4*)(&g_hs[i2 * 128 + col4]);
        float4 v3 = *(const float4*)(&g_hs[i3 * 128 + col4]);
        acc.x += v0.x + v1.x + v2.x + v3.x;
        acc.y += v0.y + v1.y + v2.y + v3.y;
        acc.z += v0.z + v1.z + v2.z + v3.z;
        acc.w += v0.w + v1.w + v2.w + v3.w;
    }
    for (; j < end; j++) {
        int i0 = g_csr[j];
        float4 v0 = *(const float4*)(&g_hs[i0 * 128 + col4]);
        acc.x += v0.x; acc.y += v0.y; acc.z += v0.z; acc.w += v0.w;
    }

    const float dv = g_dis[node];
    float4 o;
    o.x = fmaxf(dv * acc.x, 0.f);
    o.y = fmaxf(dv * acc.y, 0.f);
    o.z = fmaxf(dv * acc.z, 0.f);
    o.w = fmaxf(dv * acc.w, 0.f);

    float* out = to_buf ? g_buf : dst;
    *(float4*)(&out[node * 128 + col4]) = o;
}

// --------------------------------------------------------------------------
extern "C" void kernel_launch(void* const* d_in, const int* in_sizes, int n_in,
                              void* d_out, int out_size) {
    const float* x  = (const float*)d_in[0];
    const void*  ep = d_in[1];
    const float* W1 = (const float*)d_in[2];
    const float* b1 = (const float*)d_in[3];
    const float* W2 = (const float*)d_in[4];
    const float* b2 = (const float*)d_in[5];
    const float* W3 = (const float*)d_in[6];
    const float* b3 = (const float*)d_in[7];
    float* out = (float*)d_out;

    const int n = in_sizes[0] / D;
    const long long E = (long long)in_sizes[1] / 2;

    const int tb = 256;
    const int nb_n    = (n + tb - 1) / tb;
    const int nb_e    = (int)((E + tb - 1) / tb);
    const int nb_gemm = (n + 127) / 128;
    const int nb_agg  = (n + 7) / 8;

    k_detect<<<1, 32>>>((const int*)ep);
    k_init<<<nb_n, tb>>>(n);
    k_count<<<nb_e, tb>>>(ep, E);
    k_dis<<<nb_n, tb>>>(n);
    k_scan<<<1, 1024>>>(n);
    k_fill<<<nb_e, tb>>>(ep, E);

    k_gemm<<<nb_gemm, 256>>>(x, W1, b1, n);
    k_agg<<<nb_agg, 256>>>(out, 1, n);
    k_gemm<<<nb_gemm, 256>>>(nullptr, W2, b2, n);
    k_agg<<<nb_agg, 256>>>(out, 1, n);
    k_gemm<<<nb_gemm, 256>>>(nullptr, W3, b3, n);
    k_agg<<<nb_agg, 256>>>(out, 0, n);
}

// round 4
// speedup vs baseline: 1.8441x; 1.0687x over previous
#include <cuda_runtime.h>
#include <cuda_fp16.h>
#include <cstdint>

#define D 128
#define MAXN 100096
#define EMAX 1700000

__device__ __half g_hs[MAXN * D];   // fp16: dis[i] * (x W^T + b)
__device__ float  g_buf[MAXN * D];  // layer output -> next layer input (fp32)
__device__ int    g_deg[MAXN];
__device__ int    g_indeg[MAXN];
__device__ int    g_off[MAXN + 1];
__device__ int    g_pos[MAXN];
__device__ int    g_csr[EMAX];
__device__ float  g_dis[MAXN];
__device__ int    g_is64;

// --------------------------------------------------------------------------
__global__ void k_detect(const int* __restrict__ e32) {
    if (threadIdx.x == 0 && blockIdx.x == 0) {
        int nz = 0;
        #pragma unroll 1
        for (int i = 0; i < 64; i++) nz += (e32[2 * i + 1] != 0);
        g_is64 = (nz == 0) ? 1 : 0;
    }
}

__global__ void k_init(int n) {
    int i = blockIdx.x * blockDim.x + threadIdx.x;
    if (i < n) { g_deg[i] = 1; g_indeg[i] = 0; }
}

__global__ void k_count(const void* __restrict__ ep, long long E) {
    long long e = (long long)blockIdx.x * blockDim.x + threadIdx.x;
    if (e >= E) return;
    int r, c;
    if (g_is64) {
        const long long* p = (const long long*)ep;
        r = (int)p[e]; c = (int)p[e + E];
    } else {
        const int* p = (const int*)ep;
        r = p[e]; c = p[e + E];
    }
    atomicAdd(&g_deg[r], 1);
    atomicAdd(&g_indeg[c], 1);
}

__global__ void k_dis(int n) {
    int i = blockIdx.x * blockDim.x + threadIdx.x;
    if (i < n) g_dis[i] = rsqrtf((float)g_deg[i]);
}

__global__ __launch_bounds__(1024) void k_scan(int n) {
    __shared__ int s[1024];
    const int t = threadIdx.x;
    const int chunk = (n + 1023) / 1024;
    const int start = t * chunk;
    const int end = min(start + chunk, n);
    int sum = 0;
    for (int i = start; i < end; i++) sum += g_indeg[i];
    s[t] = sum;
    __syncthreads();
    for (int o = 1; o < 1024; o <<= 1) {
        int v = (t >= o) ? s[t - o] : 0;
        __syncthreads();
        s[t] += v;
        __syncthreads();
    }
    int run = (t == 0) ? 0 : s[t - 1];
    for (int i = start; i < end; i++) {
        g_off[i] = run;
        g_pos[i] = run;
        run += g_indeg[i];
    }
    if (t == 1023) g_off[n] = s[1023];
}

__global__ void k_fill(const void* __restrict__ ep, long long E) {
    long long e = (long long)blockIdx.x * blockDim.x + threadIdx.x;
    if (e >= E) return;
    int r, c;
    if (g_is64) {
        const long long* p = (const long long*)ep;
        r = (int)p[e]; c = (int)p[e + E];
    } else {
        const int* p = (const int*)ep;
        r = p[e]; c = p[e + E];
    }
    int p = atomicAdd(&g_pos[c], 1);
    g_csr[p] = r;
}

// --------------------------------------------------------------------------
// 3xTF32 tensor-core GEMM, hi/lo interleaved float2 smem (64-bit LDS feed).
// g_hs[i,j] = (half) dis[i] * ((X W^T)[i,j] + b[j])
// BM=BN=128, BK=16, 256 threads (8 warps 4x2), warp tile 32x64
// --------------------------------------------------------------------------
__device__ __forceinline__ float tf32_rna(float x) {
    uint32_t u;
    asm("cvt.rna.tf32.f32 %0, %1;" : "=r"(u) : "f"(x));
    return __uint_as_float(u);
}

__device__ __forceinline__ void mma_tf32(float c[4], const float a[4], const float b[2]) {
    const uint32_t* A = reinterpret_cast<const uint32_t*>(a);
    const uint32_t* Bp = reinterpret_cast<const uint32_t*>(b);
    asm volatile(
        "mma.sync.aligned.m16n8k8.row.col.f32.tf32.tf32.f32 "
        "{%0,%1,%2,%3}, {%4,%5,%6,%7}, {%8,%9}, {%0,%1,%2,%3};"
        : "+f"(c[0]), "+f"(c[1]), "+f"(c[2]), "+f"(c[3])
        : "r"(A[0]), "r"(A[1]), "r"(A[2]), "r"(A[3]), "r"(Bp[0]), "r"(Bp[1]));
}

#define BK 16
#define SP2 132

__global__ __launch_bounds__(256) void k_gemm(const float* __restrict__ Xin,
                                              const float* __restrict__ W,
                                              const float* __restrict__ Bv,
                                              int n) {
    const float* X = Xin ? Xin : g_buf;
    __shared__ float2 sX2[BK][SP2];   // {hi, lo}
    __shared__ float2 sW2[BK][SP2];

    const int tid  = threadIdx.x;
    const int lane = tid & 31;
    const int wid  = tid >> 5;
    const int warpRow = wid >> 1;   // 0..3
    const int warpCol = wid & 1;    // 0..1
    const int row0 = blockIdx.x * 128;
    const int lr = lane >> 2;       // 0..7
    const int lq = lane & 3;        // 0..3

    float c[2][8][4];
    #pragma unroll
    for (int mt = 0; mt < 2; mt++)
        #pragma unroll
        for (int nt = 0; nt < 8; nt++)
            #pragma unroll
            for (int q = 0; q < 4; q++) c[mt][nt][q] = 0.f;

    for (int k0 = 0; k0 < 128; k0 += BK) {
        #pragma unroll
        for (int it = 0; it < 2; it++) {
            int idx = it * 256 + tid;       // 0..511
            int r = idx >> 2;               // 0..127
            int kq = (idx & 3) * 4;         // 0,4,8,12
            int gr = row0 + r;
            float4 xv = (gr < n) ? *(const float4*)&X[(long long)gr * 128 + k0 + kq]
                                 : make_float4(0.f, 0.f, 0.f, 0.f);
            float4 wv = *(const float4*)&W[r * 128 + k0 + kq];
            float xe[4] = {xv.x, xv.y, xv.z, xv.w};
            float we[4] = {wv.x, wv.y, wv.z, wv.w};
            #pragma unroll
            for (int q = 0; q < 4; q++) {
                float xh = tf32_rna(xe[q]);
                float wh = tf32_rna(we[q]);
                sX2[kq + q][r] = make_float2(xh, tf32_rna(xe[q] - xh));
                sW2[kq + q][r] = make_float2(wh, tf32_rna(we[q] - wh));
            }
        }
        __syncthreads();

        #pragma unroll
        for (int kk = 0; kk < BK; kk += 8) {
            float ahi[2][4], alo[2][4];
            #pragma unroll
            for (int mt = 0; mt < 2; mt++) {
                int r = warpRow * 32 + mt * 16 + lr;
                float2 a0 = sX2[kk + lq][r];
                float2 a1 = sX2[kk + lq][r + 8];
                float2 a2 = sX2[kk + lq + 4][r];
                float2 a3 = sX2[kk + lq + 4][r + 8];
                ahi[mt][0] = a0.x; alo[mt][0] = a0.y;
                ahi[mt][1] = a1.x; alo[mt][1] = a1.y;
                ahi[mt][2] = a2.x; alo[mt][2] = a2.y;
                ahi[mt][3] = a3.x; alo[mt][3] = a3.y;
            }
            #pragma unroll
            for (int nt = 0; nt < 8; nt++) {
                int col = warpCol * 64 + nt * 8 + lr;
                float2 b0 = sW2[kk + lq][col];
                float2 b1 = sW2[kk + lq + 4][col];
                float bhi[2] = {b0.x, b1.x};
                float blo[2] = {b0.y, b1.y};
                #pragma unroll
                for (int mt = 0; mt < 2; mt++) {
                    mma_tf32(c[mt][nt], ahi[mt], bhi);
                    mma_tf32(c[mt][nt], ahi[mt], blo);
                    mma_tf32(c[mt][nt], alo[mt], bhi);
                }
            }
        }
        __syncthreads();
    }

    // epilogue: hs[gi, col] = (half) dis[gi] * (c + bias[col])
    #pragma unroll
    for (int mt = 0; mt < 2; mt++) {
        #pragma unroll
        for (int half2i = 0; half2i < 2; half2i++) {
            int gi = row0 + warpRow * 32 + mt * 16 + lr + half2i * 8;
            if (gi >= n) continue;
            float dv = g_dis[gi];
            #pragma unroll
            for (int nt = 0; nt < 8; nt++) {
                int col = warpCol * 64 + nt * 8 + lq * 2;
                float ox = dv * (c[mt][nt][half2i * 2 + 0] + Bv[col]);
                float oy = dv * (c[mt][nt][half2i * 2 + 1] + Bv[col + 1]);
                *(__half2*)&g_hs[(long long)gi * 128 + col] = __floats2half2_rn(ox, oy);
            }
        }
    }
}

// --------------------------------------------------------------------------
// Pull aggregation fused with finalize (fp16 gather, fp32 accumulate):
// out[c,:] = relu( dis[c] * ( sum_{src in CSR[c]} hs[src,:] + hs[c,:] ) )
// one warp per node, 4 halves (uint2) per lane
// --------------------------------------------------------------------------
__global__ __launch_bounds__(256) void k_agg(float* __restrict__ dst,
                                             int to_buf, int n) {
    const int node = blockIdx.x * 8 + (threadIdx.x >> 5);
    if (node >= n) return;
    const int lane = threadIdx.x & 31;
    const int col4 = lane * 4;

    const int beg = g_off[node];
    const int end = g_off[node + 1];

    // self-loop term
    const __half2* sp = (const __half2*)&g_hs[(long long)node * 128 + col4];
    float2 a01 = __half22float2(sp[0]);
    float2 a23 = __half22float2(sp[1]);
    float ax = a01.x, ay = a01.y, az = a23.x, aw = a23.y;

    int j = beg;
    for (; j + 4 <= end; j += 4) {
        int i0 = g_csr[j + 0];
        int i1 = g_csr[j + 1];
        int i2 = g_csr[j + 2];
        int i3 = g_csr[j + 3];
        const __half2* p0 = (const __half2*)&g_hs[(long long)i0 * 128 + col4];
        const __half2* p1 = (const __half2*)&g_hs[(long long)i1 * 128 + col4];
        const __half2* p2 = (const __half2*)&g_hs[(long long)i2 * 128 + col4];
        const __half2* p3 = (const __half2*)&g_hs[(long long)i3 * 128 + col4];
        float2 v;
        v = __half22float2(p0[0]); ax += v.x; ay += v.y;
        v = __half22float2(p0[1]); az += v.x; aw += v.y;
        v = __half22float2(p1[0]); ax += v.x; ay += v.y;
        v = __half22float2(p1[1]); az += v.x; aw += v.y;
        v = __half22float2(p2[0]); ax += v.x; ay += v.y;
        v = __half22float2(p2[1]); az += v.x; aw += v.y;
        v = __half22float2(p3[0]); ax += v.x; ay += v.y;
        v = __half22float2(p3[1]); az += v.x; aw += v.y;
    }
    for (; j < end; j++) {
        int i0 = g_csr[j];
        const __half2* p0 = (const __half2*)&g_hs[(long long)i0 * 128 + col4];
        float2 v;
        v = __half22float2(p0[0]); ax += v.x; ay += v.y;
        v = __half22float2(p0[1]); az += v.x; aw += v.y;
    }

    const float dv = g_dis[node];
    float4 o;
    o.x = fmaxf(dv * ax, 0.f);
    o.y = fmaxf(dv * ay, 0.f);
    o.z = fmaxf(dv * az, 0.f);
    o.w = fmaxf(dv * aw, 0.f);

    float* out = to_buf ? g_buf : dst;
    *(float4*)(&out[(long long)node * 128 + col4]) = o;
}

// --------------------------------------------------------------------------
extern "C" void kernel_launch(void* const* d_in, const int* in_sizes, int n_in,
                              void* d_out, int out_size) {
    const float* x  = (const float*)d_in[0];
    const void*  ep = d_in[1];
    const float* W1 = (const float*)d_in[2];
    const float* b1 = (const float*)d_in[3];
    const float* W2 = (const float*)d_in[4];
    const float* b2 = (const float*)d_in[5];
    const float* W3 = (const float*)d_in[6];
    const float* b3 = (const float*)d_in[7];
    float* out = (float*)d_out;

    const int n = in_sizes[0] / D;
    const long long E = (long long)in_sizes[1] / 2;

    const int tb = 256;
    const int nb_n    = (n + tb - 1) / tb;
    const int nb_e    = (int)((E + tb - 1) / tb);
    const int nb_gemm = (n + 127) / 128;
    const int nb_agg  = (n + 7) / 8;

    k_detect<<<1, 32>>>((const int*)ep);
    k_init<<<nb_n, tb>>>(n);
    k_count<<<nb_e, tb>>>(ep, E);
    k_dis<<<nb_n, tb>>>(n);
    k_scan<<<1, 1024>>>(n);
    k_fill<<<nb_e, tb>>>(ep, E);

    k_gemm<<<nb_gemm, 256>>>(x, W1, b1, n);
    k_agg<<<nb_agg, 256>>>(out, 1, n);
    k_gemm<<<nb_gemm, 256>>>(nullptr, W2, b2, n);
    k_agg<<<nb_agg, 256>>>(out, 1, n);
    k_gemm<<<nb_gemm, 256>>>(nullptr, W3, b3, n);
    k_agg<<<nb_agg, 256>>>(out, 0, n);
}